// round 13
// baseline (speedup 1.0000x reference)
#include <cuda_runtime.h>
#include <cuda_fp16.h>
#include <cstdint>

// Problem constants
#define NN 100000
#define EE 1600000
#define HID 128
#define NCLS 40
#define GG 782              // gemm blocks = ceil(NN/128)
#define PAD 128             // bucket slots per destination node

// ---------------- mma.sync / cp.async helpers ----------------
__device__ __forceinline__ void ldsm_x4(uint32_t addr, uint32_t& r0, uint32_t& r1,
                                        uint32_t& r2, uint32_t& r3) {
    asm volatile("ldmatrix.sync.aligned.m8n8.x4.shared.b16 {%0,%1,%2,%3}, [%4];"
                 : "=r"(r0), "=r"(r1), "=r"(r2), "=r"(r3) : "r"(addr));
}
__device__ __forceinline__ void ldsm_x4_t(uint32_t addr, uint32_t& r0, uint32_t& r1,
                                          uint32_t& r2, uint32_t& r3) {
    asm volatile("ldmatrix.sync.aligned.m8n8.x4.trans.shared.b16 {%0,%1,%2,%3}, [%4];"
                 : "=r"(r0), "=r"(r1), "=r"(r2), "=r"(r3) : "r"(addr));
}
__device__ __forceinline__ void mma16816(float c[4], const uint32_t a[4],
                                         uint32_t b0, uint32_t b1) {
    asm volatile(
        "mma.sync.aligned.m16n8k16.row.col.f32.f16.f16.f32 "
        "{%0,%1,%2,%3}, {%4,%5,%6,%7}, {%8,%9}, {%0,%1,%2,%3};"
        : "+f"(c[0]), "+f"(c[1]), "+f"(c[2]), "+f"(c[3])
        : "r"(a[0]), "r"(a[1]), "r"(a[2]), "r"(a[3]), "r"(b0), "r"(b1));
}
__device__ __forceinline__ void cpa16(uint32_t d, const void* s, bool p) {
    asm volatile("cp.async.cg.shared.global [%0], [%1], 16, %2;"
                 :: "r"(d), "l"(s), "r"(p ? 16 : 0));
}
__device__ __forceinline__ void cpcommit() { asm volatile("cp.async.commit_group;"); }

// ---------------- device scratch (static; no cudaMalloc allowed) ----------------
__device__ __half g_xh [(size_t)NN * HID];  // fp16 copy of x
__device__ __half g_w1h[HID * HID];
__device__ __half g_w2h[HID * HID];
__device__ __half g_tmp[(size_t)NN * HID];  // fp16 raw messages XW (unscaled)
__device__ __half g_h1h[(size_t)NN * HID];  // layer-1 hidden, fp16
__device__ __half g_h2h[(size_t)NN * HID];  // layer-2 hidden, fp16 (head input)
__device__ float  g_dinv[NN];
__device__ int    g_cursor[NN];             // in-degree counter (excl self loop)
__device__ int    g_colp[(size_t)NN * PAD]; // padded buckets: sources per dst
__device__ int    g_fmt;                    // 1 = edge_index is int64, 0 = int32

// low word of edge idx (int64 ids < 2^31: low word is the value)
__device__ __forceinline__ int edge_at(const void* __restrict__ ei, size_t idx) {
    if (g_fmt) return ((const int*)ei)[idx * 2];
    return ((const int*)ei)[idx];
}

// ---------------- K0: fp16 converts + cursor reset + dtype detect ----------------
__global__ void k_init(const float* __restrict__ x, const float* __restrict__ W1,
                       const float* __restrict__ W2, const int* __restrict__ ei) {
    int i = blockIdx.x * blockDim.x + threadIdx.x;   // grid covers NN*HID/4 = 3.2M
    {
        float4 v = ((const float4*)x)[i];
        half2 a = __floats2half2_rn(v.x, v.y), b = __floats2half2_rn(v.z, v.w);
        uint2 p; p.x = *(unsigned*)&a; p.y = *(unsigned*)&b;
        ((uint2*)g_xh)[i] = p;
    }
    if (i < HID * HID / 4) {
        float4 v = ((const float4*)W1)[i];
        half2 a = __floats2half2_rn(v.x, v.y), b = __floats2half2_rn(v.z, v.w);
        uint2 p; p.x = *(unsigned*)&a; p.y = *(unsigned*)&b;
        ((uint2*)g_w1h)[i] = p;
        float4 w = ((const float4*)W2)[i];
        half2 c = __floats2half2_rn(w.x, w.y), d = __floats2half2_rn(w.z, w.w);
        uint2 q; q.x = *(unsigned*)&c; q.y = *(unsigned*)&d;
        ((uint2*)g_w2h)[i] = q;
    }
    if (i < NN) g_cursor[i] = 0;
    if (i == 0) {
        int is64 = 1;
        #pragma unroll
        for (int j = 1; j < 64; j += 2) is64 &= (ei[j] == 0);
        g_fmt = is64;
    }
}

// ---------------- tensor-core GEMM body (cp.async double-buffered, raw output) ----
__device__ __forceinline__ void gemm_body(const __half* __restrict__ Ah,
                                          const __half* __restrict__ Wm,
                                          int bid, __half* AsBuf, __half* WsBuf) {
    const int ABUF = 128 * 40 * 2;   // bytes per A buffer
    const int WBUF = 32 * 136 * 2;   // bytes per W buffer
    int t = threadIdx.x, lane = t & 31, wid = t >> 5;
    int m0 = bid * 128;
    int wm = (wid & 3) * 32;
    int wn = (wid >> 2) * 64;

    float acc[2][8][4];
    #pragma unroll
    for (int mt = 0; mt < 2; mt++)
        #pragma unroll
        for (int nt = 0; nt < 8; nt++)
            #pragma unroll
            for (int q = 0; q < 4; q++) acc[mt][nt][q] = 0.f;

    uint32_t as_base = (uint32_t)__cvta_generic_to_shared(AsBuf);
    uint32_t ws_base = (uint32_t)__cvta_generic_to_shared(WsBuf);

    int sr = t >> 1, sseg = (t & 1) * 2;
    int swr = t >> 3, swseg = (t & 7) * 2;
    int sgrow = m0 + sr;
    bool sp = sgrow < NN;
    const __half* aSrc = Ah + (size_t)sgrow * HID + sseg * 8;
    const __half* wSrc = Wm + (size_t)swr * HID + swseg * 8;
    uint32_t aDst = as_base + sr * 80 + sseg * 16;
    uint32_t wDst = ws_base + swr * 272 + swseg * 16;

    int a_row = wm + (lane & 15);
    int a_col = (lane >> 4) * 8;
    int g = lane >> 3;
    int b_krow = (lane & 7) + (g >> 1) * 8;
    int b_ncol = wn + (g & 1) * 8;

    cpa16(aDst, aSrc, sp);
    cpa16(aDst + 16, aSrc + 8, sp);
    cpa16(wDst, wSrc, true);
    cpa16(wDst + 16, wSrc + 8, true);
    cpcommit();

    #pragma unroll
    for (int i = 0; i < 4; i++) {
        if (i < 3) {
            int buf = (i + 1) & 1, kc = (i + 1) * 32;
            cpa16(aDst + buf * ABUF, aSrc + kc, sp);
            cpa16(aDst + buf * ABUF + 16, aSrc + kc + 8, sp);
            cpa16(wDst + buf * WBUF, wSrc + (size_t)kc * HID, true);
            cpa16(wDst + buf * WBUF + 16, wSrc + (size_t)kc * HID + 8, true);
            cpcommit();
            asm volatile("cp.async.wait_group 1;" ::: "memory");
        } else {
            asm volatile("cp.async.wait_group 0;" ::: "memory");
        }
        __syncthreads();
        int cur = i & 1;
        uint32_t a_b = as_base + cur * ABUF;
        uint32_t w_b = ws_base + cur * WBUF;

        #pragma unroll
        for (int ks = 0; ks < 32; ks += 16) {
            uint32_t a[2][4];
            #pragma unroll
            for (int mt = 0; mt < 2; mt++) {
                uint32_t addr = a_b + ((a_row + mt * 16) * 40 + ks + a_col) * 2;
                ldsm_x4(addr, a[mt][0], a[mt][1], a[mt][2], a[mt][3]);
            }
            uint32_t b[8][2];
            #pragma unroll
            for (int ntq = 0; ntq < 4; ntq++) {
                uint32_t addr = w_b + ((ks + b_krow) * 136 + b_ncol + ntq * 16) * 2;
                uint32_t r0, r1, r2, r3;
                ldsm_x4_t(addr, r0, r1, r2, r3);
                b[ntq * 2][0] = r0; b[ntq * 2 + 1][0] = r1;
                b[ntq * 2][1] = r2; b[ntq * 2 + 1][1] = r3;
            }
            #pragma unroll
            for (int mt = 0; mt < 2; mt++)
                #pragma unroll
                for (int nt = 0; nt < 8; nt++)
                    mma16816(acc[mt][nt], a[mt], b[nt][0], b[nt][1]);
        }
        __syncthreads();
    }

    // epilogue: store RAW fp16 (scaling deferred to SpMM)
    int qr = lane >> 2, qc = (lane & 3) * 2;
    #pragma unroll
    for (int mt = 0; mt < 2; mt++) {
        int row_lo = m0 + wm + mt * 16 + qr;
        int row_hi = row_lo + 8;
        #pragma unroll
        for (int nt = 0; nt < 8; nt++) {
            int colg = wn + nt * 8 + qc;
            if (row_lo < NN) {
                half2 h = __floats2half2_rn(acc[mt][nt][0], acc[mt][nt][1]);
                *(half2*)(g_tmp + (size_t)row_lo * HID + colg) = h;
            }
            if (row_hi < NN) {
                half2 h = __floats2half2_rn(acc[mt][nt][2], acc[mt][nt][3]);
                *(half2*)(g_tmp + (size_t)row_hi * HID + colg) = h;
            }
        }
    }
}

// ---------------- K1: GEMM layer-1 || padded bucket fill (counts degrees too) ----
__global__ void __launch_bounds__(256, 2) k_mega1(const void* __restrict__ ei) {
    __shared__ __align__(16) __half As[2][128][40];
    __shared__ __align__(16) __half Ws[2][32][136];
    if (blockIdx.x < GG) {
        gemm_body(g_xh, g_w1h, blockIdx.x, &As[0][0][0], &Ws[0][0][0]);
    } else {
        int e = (blockIdx.x - GG) * 256 + threadIdx.x;
        if (e < EE) {
            int s = edge_at(ei, e);
            int d = edge_at(ei, (size_t)EE + e);
            if ((unsigned)d < NN) {
                int pos = atomicAdd(&g_cursor[d], 1);
                int c = ((unsigned)s < NN) ? s : d;
                if (pos < PAD) g_colp[(size_t)d * PAD + pos] = c;
            }
        }
    }
}

// ---------------- K2: dinv from degrees ----------------
__global__ void k_dinv() {
    int i = blockIdx.x * blockDim.x + threadIdx.x;
    if (i < NN) g_dinv[i] = rsqrtf((float)g_cursor[i] + 1.0f);   // +1 self loop
}

__global__ void __launch_bounds__(256, 2) k_gemm2() {
    __shared__ __align__(16) __half As[2][128][40];
    __shared__ __align__(16) __half Ws[2][32][136];
    gemm_body(g_h1h, g_w2h, blockIdx.x, &As[0][0][0], &Ws[0][0][0]);
}

// ---------------- SpMM: out[d] = relu(dinv[d]*(Σ dinv[s]*msg[s] + dinv[d]*msg[d]) + b)
// DST=0: write fp16 g_h1h. DST=1: write fp32 outp (h2) + fp16 g_h2h.
template<int DST>
__global__ void k_spmm(const float* __restrict__ bias, float* __restrict__ outp) {
    int gw = (blockIdx.x * blockDim.x + threadIdx.x) >> 5;
    int lane = threadIdx.x & 31;
    if (gw >= NN) return;
    int cnt = g_cursor[gw];
    if (cnt > PAD) cnt = PAD;
    const int* cols = g_colp + (size_t)gw * PAD;
    const __half* tmp = (const __half*)g_tmp;
    float dv = g_dinv[gw];

    float4 acc;
    {   // self-loop message, weight dinv[d]
        uint2 u = *(const uint2*)(tmp + (size_t)gw * HID + lane * 4);
        float2 a = __half22float2(*(half2*)&u.x), b = __half22float2(*(half2*)&u.y);
        acc = make_float4(dv * a.x, dv * a.y, dv * b.x, dv * b.y);
    }
    int j = 0;
    for (; j + 4 <= cnt; j += 4) {
        int s0 = cols[j], s1 = cols[j + 1], s2 = cols[j + 2], s3 = cols[j + 3];
        float w0 = g_dinv[s0], w1 = g_dinv[s1], w2 = g_dinv[s2], w3 = g_dinv[s3];
        uint2 u0 = *(const uint2*)(tmp + (size_t)s0 * HID + lane * 4);
        uint2 u1 = *(const uint2*)(tmp + (size_t)s1 * HID + lane * 4);
        uint2 u2 = *(const uint2*)(tmp + (size_t)s2 * HID + lane * 4);
        uint2 u3 = *(const uint2*)(tmp + (size_t)s3 * HID + lane * 4);
        float2 a0 = __half22float2(*(half2*)&u0.x), b0 = __half22float2(*(half2*)&u0.y);
        float2 a1 = __half22float2(*(half2*)&u1.x), b1 = __half22float2(*(half2*)&u1.y);
        float2 a2 = __half22float2(*(half2*)&u2.x), b2 = __half22float2(*(half2*)&u2.y);
        float2 a3 = __half22float2(*(half2*)&u3.x), b3 = __half22float2(*(half2*)&u3.y);
        acc.x += w0 * a0.x + w1 * a1.x + w2 * a2.x + w3 * a3.x;
        acc.y += w0 * a0.y + w1 * a1.y + w2 * a2.y + w3 * a3.y;
        acc.z += w0 * b0.x + w1 * b1.x + w2 * b2.x + w3 * b3.x;
        acc.w += w0 * b0.y + w1 * b1.y + w2 * b2.y + w3 * b3.y;
    }
    for (; j < cnt; j++) {
        int s = cols[j];
        float w = g_dinv[s];
        uint2 u = *(const uint2*)(tmp + (size_t)s * HID + lane * 4);
        float2 a = __half22float2(*(half2*)&u.x), b = __half22float2(*(half2*)&u.y);
        acc.x += w * a.x; acc.y += w * a.y; acc.z += w * b.x; acc.w += w * b.y;
    }

    float4 b4 = *(const float4*)(bias + lane * 4);
    float4 o;
    o.x = fmaxf(fmaf(acc.x, dv, b4.x), 0.f);
    o.y = fmaxf(fmaf(acc.y, dv, b4.y), 0.f);
    o.z = fmaxf(fmaf(acc.z, dv, b4.z), 0.f);
    o.w = fmaxf(fmaf(acc.w, dv, b4.w), 0.f);

    half2 ha = __floats2half2_rn(o.x, o.y);
    half2 hb = __floats2half2_rn(o.z, o.w);
    uint2 pk;
    pk.x = *(unsigned*)&ha; pk.y = *(unsigned*)&hb;
    if (DST == 0) {
        *(uint2*)(g_h1h + (size_t)gw * HID + lane * 4) = pk;
    } else {
        *(float4*)(outp + (size_t)gw * HID + lane * 4) = o;
        *(uint2*)(g_h2h + (size_t)gw * HID + lane * 4) = pk;
    }
}

// ---------------- head GEMM (HMMA): S[m][c] = h2[m][:] . Wh[:][c] + bh[c] ----------------
__global__ void __launch_bounds__(256)
k_head(const float* __restrict__ Wh, const float* __restrict__ bh, float* __restrict__ S) {
    __shared__ __align__(16) __half As[128][72];
    __shared__ __align__(16) __half Wsh[128][56];
    int t = threadIdx.x, lane = t & 31, wid = t >> 5;
    int m0 = blockIdx.x * 128;
    int wm = wid * 16;

    for (int i = t; i < 128 * 24; i += 256) {
        int r = i / 24, c2 = (i % 24) * 2;
        float lo = (c2 < NCLS) ? Wh[(size_t)r * NCLS + c2] : 0.f;
        float hi = (c2 + 1 < NCLS) ? Wh[(size_t)r * NCLS + c2 + 1] : 0.f;
        *(half2*)&Wsh[r][c2] = __floats2half2_rn(lo, hi);
    }

    float acc[6][4];
    #pragma unroll
    for (int nt = 0; nt < 6; nt++)
        #pragma unroll
        for (int q = 0; q < 4; q++) acc[nt][q] = 0.f;

    uint32_t as_base = (uint32_t)__cvta_generic_to_shared(&As[0][0]);
    uint32_t ws_base = (uint32_t)__cvta_generic_to_shared(&Wsh[0][0]);
    int a_row = wm + (lane & 15);
    int a_col = (lane >> 4) * 8;
    int g = lane >> 3;
    int b_krow = (lane & 7) + (g >> 1) * 8;
    int b_ncol = (g & 1) * 8;

    #pragma unroll
    for (int kc = 0; kc < HID; kc += 64) {
        {
            int r = t >> 1, cs = (t & 1) * 32;
            int grow = m0 + r;
            uint4 p0 = make_uint4(0,0,0,0), p1 = p0, p2 = p0, p3 = p0;
            if (grow < NN) {
                const uint4* src = (const uint4*)(g_h2h + (size_t)grow * HID + kc + cs);
                p0 = src[0]; p1 = src[1]; p2 = src[2]; p3 = src[3];
            }
            *(uint4*)&As[r][cs]      = p0;
            *(uint4*)&As[r][cs + 8]  = p1;
            *(uint4*)&As[r][cs + 16] = p2;
            *(uint4*)&As[r][cs + 24] = p3;
        }
        __syncthreads();

        #pragma unroll
        for (int ks = 0; ks < 64; ks += 16) {
            uint32_t a[4];
            ldsm_x4(as_base + (a_row * 72 + ks + a_col) * 2, a[0], a[1], a[2], a[3]);
            uint32_t b[6][2];
            #pragma unroll
            for (int ntq = 0; ntq < 3; ntq++) {
                uint32_t addr = ws_base + ((kc + ks + b_krow) * 56 + b_ncol + ntq * 16) * 2;
                uint32_t r0, r1, r2, r3;
                ldsm_x4_t(addr, r0, r1, r2, r3);
                b[ntq * 2][0] = r0; b[ntq * 2 + 1][0] = r1;
                b[ntq * 2][1] = r2; b[ntq * 2 + 1][1] = r3;
            }
            #pragma unroll
            for (int nt = 0; nt < 6; nt++)
                mma16816(acc[nt], a, b[nt][0], b[nt][1]);
        }
        __syncthreads();
    }

    int qr = lane >> 2, qc = (lane & 3) * 2;
    int row_lo = m0 + wm + qr, row_hi = row_lo + 8;
    #pragma unroll
    for (int nt = 0; nt < 5; nt++) {
        int col = nt * 8 + qc;
        float blo = bh[col], bhi = bh[col + 1];
        if (row_lo < NN) {
            S[(size_t)row_lo * NCLS + col]     = acc[nt][0] + blo;
            S[(size_t)row_lo * NCLS + col + 1] = acc[nt][1] + bhi;
        }
        if (row_hi < NN) {
            S[(size_t)row_hi * NCLS + col]     = acc[nt][2] + blo;
            S[(size_t)row_hi * NCLS + col + 1] = acc[nt][3] + bhi;
        }
    }
}

// ---------------- launch ----------------
extern "C" void kernel_launch(void* const* d_in, const int* in_sizes, int n_in,
                              void* d_out, int out_size) {
    const float* x   = (const float*)d_in[0];
    const void*  ei  = d_in[1];                 // int32 or int64, detected on device
    const float* W1  = (const float*)d_in[2];
    const float* b1  = (const float*)d_in[3];
    const float* W2  = (const float*)d_in[4];
    const float* b2  = (const float*)d_in[5];
    const float* Wh  = (const float*)d_in[6];
    const float* bh  = (const float*)d_in[7];

    float* out = (float*)d_out;
    float* scores = out;                       // [NN, 40]
    float* h2 = out + (size_t)NN * NCLS;       // [NN, 128]

    const int TB = 256;
    int spmm_grid = (NN * 32 + TB - 1) / TB;
    int fill_blocks = (EE + TB - 1) / TB;      // 6250

    k_init<<<NN * HID / 4 / TB, TB>>>(x, W1, W2, (const int*)ei);
    k_mega1<<<GG + fill_blocks, TB>>>(ei);     // GEMM1 || bucket fill
    k_dinv<<<(NN + TB - 1) / TB, TB>>>();
    k_spmm<0><<<spmm_grid, TB>>>(b1, nullptr);
    k_gemm2<<<GG, TB>>>();
    k_spmm<1><<<spmm_grid, TB>>>(b2, h2);
    k_head<<<GG, TB>>>(Wh, bh, scores);
}

// round 14
// speedup vs baseline: 1.1791x; 1.1791x over previous
#include <cuda_runtime.h>
#include <cuda_fp16.h>
#include <cstdint>

// Problem constants
#define NN 100000
#define EE 1600000
#define HID 128
#define NCLS 40
#define GG 782              // gemm blocks = ceil(NN/128)
#define PAD 128             // bucket slots per destination node
#define CONVB 12500         // conversion blocks in k_init (NN*HID/4/256)
#define FILLB 6250          // fill blocks in k_init (EE/256)
#define ZB 391              // cursor-zero blocks appended to k_head

// ---------------- mma.sync / cp.async helpers ----------------
__device__ __forceinline__ void ldsm_x4(uint32_t addr, uint32_t& r0, uint32_t& r1,
                                        uint32_t& r2, uint32_t& r3) {
    asm volatile("ldmatrix.sync.aligned.m8n8.x4.shared.b16 {%0,%1,%2,%3}, [%4];"
                 : "=r"(r0), "=r"(r1), "=r"(r2), "=r"(r3) : "r"(addr));
}
__device__ __forceinline__ void ldsm_x4_t(uint32_t addr, uint32_t& r0, uint32_t& r1,
                                          uint32_t& r2, uint32_t& r3) {
    asm volatile("ldmatrix.sync.aligned.m8n8.x4.trans.shared.b16 {%0,%1,%2,%3}, [%4];"
                 : "=r"(r0), "=r"(r1), "=r"(r2), "=r"(r3) : "r"(addr));
}
__device__ __forceinline__ void mma16816(float c[4], const uint32_t a[4],
                                         uint32_t b0, uint32_t b1) {
    asm volatile(
        "mma.sync.aligned.m16n8k16.row.col.f32.f16.f16.f32 "
        "{%0,%1,%2,%3}, {%4,%5,%6,%7}, {%8,%9}, {%0,%1,%2,%3};"
        : "+f"(c[0]), "+f"(c[1]), "+f"(c[2]), "+f"(c[3])
        : "r"(a[0]), "r"(a[1]), "r"(a[2]), "r"(a[3]), "r"(b0), "r"(b1));
}
__device__ __forceinline__ void cpa16(uint32_t d, const void* s, bool p) {
    asm volatile("cp.async.cg.shared.global [%0], [%1], 16, %2;"
                 :: "r"(d), "l"(s), "r"(p ? 16 : 0));
}
__device__ __forceinline__ void cpcommit() { asm volatile("cp.async.commit_group;"); }

// ---------------- device scratch (static; no cudaMalloc allowed) ----------------
__device__ __half g_xh [(size_t)NN * HID];  // fp16 copy of x
__device__ __half g_w1h[HID * HID];
__device__ __half g_w2h[HID * HID];
__device__ __half g_tmp[(size_t)NN * HID];  // fp16 messages, pre-scaled by dinv[src]
__device__ __half g_h1h[(size_t)NN * HID];  // layer-1 hidden, fp16
__device__ __half g_h2h[(size_t)NN * HID];  // layer-2 hidden, fp16 (head input)
__device__ int    g_cursor[NN];             // in-degree counter (excl self loop);
                                            // ZERO at sequence entry (zero-init /
                                            // trailing reset blocks in k_head)
__device__ int    g_colp[(size_t)NN * PAD]; // padded buckets: sources per dst

// ---------------- K0: fp16 converts || bucket fill ----------------
__global__ void __launch_bounds__(256)
k_init(const float* __restrict__ x, const float* __restrict__ W1,
       const float* __restrict__ W2, const void* __restrict__ ei) {
    if (blockIdx.x < CONVB) {
        int i = blockIdx.x * blockDim.x + threadIdx.x;   // 0 .. NN*HID/4
        {
            float4 v = ((const float4*)x)[i];
            half2 a = __floats2half2_rn(v.x, v.y), b = __floats2half2_rn(v.z, v.w);
            uint2 p; p.x = *(unsigned*)&a; p.y = *(unsigned*)&b;
            ((uint2*)g_xh)[i] = p;
        }
        if (i < HID * HID / 4) {
            float4 v = ((const float4*)W1)[i];
            half2 a = __floats2half2_rn(v.x, v.y), b = __floats2half2_rn(v.z, v.w);
            uint2 p; p.x = *(unsigned*)&a; p.y = *(unsigned*)&b;
            ((uint2*)g_w1h)[i] = p;
            float4 w = ((const float4*)W2)[i];
            half2 c = __floats2half2_rn(w.x, w.y), d = __floats2half2_rn(w.z, w.w);
            uint2 q; q.x = *(unsigned*)&c; q.y = *(unsigned*)&d;
            ((uint2*)g_w2h)[i] = q;
        }
    } else {
        // bucket fill; per-block edge-dtype detection (no global ordering hazard)
        __shared__ int sfmt;
        if (threadIdx.x == 0) {
            const int* w = (const int*)ei;
            int is64 = 1;
            #pragma unroll
            for (int j = 1; j < 64; j += 2) is64 &= (w[j] == 0);
            sfmt = is64;
        }
        __syncthreads();
        int e = (blockIdx.x - CONVB) * 256 + threadIdx.x;
        if (e < EE) {
            const int* w = (const int*)ei;
            int s, d;
            if (sfmt) { s = w[(size_t)e * 2]; d = w[((size_t)EE + e) * 2]; }
            else      { s = w[e];             d = w[(size_t)EE + e]; }
            if ((unsigned)d < NN) {
                int pos = atomicAdd(&g_cursor[d], 1);
                int c = ((unsigned)s < NN) ? s : d;
                if (pos < PAD) g_colp[(size_t)d * PAD + pos] = c;
            }
        }
    }
}

// ---------------- tensor-core GEMM body (cp.async double-buffered) ----------------
// g_tmp[m][n] = half((A.W)[m][n] * rsqrt(deg[m])); deg = cursor+1 (self loop).
__device__ __forceinline__ void gemm_body(const __half* __restrict__ Ah,
                                          const __half* __restrict__ Wm,
                                          int bid, __half* AsBuf, __half* WsBuf) {
    const int ABUF = 128 * 40 * 2;   // bytes per A buffer
    const int WBUF = 32 * 136 * 2;   // bytes per W buffer
    int t = threadIdx.x, lane = t & 31, wid = t >> 5;
    int m0 = bid * 128;
    int wm = (wid & 3) * 32;
    int wn = (wid >> 2) * 64;

    float acc[2][8][4];
    #pragma unroll
    for (int mt = 0; mt < 2; mt++)
        #pragma unroll
        for (int nt = 0; nt < 8; nt++)
            #pragma unroll
            for (int q = 0; q < 4; q++) acc[mt][nt][q] = 0.f;

    uint32_t as_base = (uint32_t)__cvta_generic_to_shared(AsBuf);
    uint32_t ws_base = (uint32_t)__cvta_generic_to_shared(WsBuf);

    int sr = t >> 1, sseg = (t & 1) * 2;
    int swr = t >> 3, swseg = (t & 7) * 2;
    int sgrow = m0 + sr;
    bool sp = sgrow < NN;
    const __half* aSrc = Ah + (size_t)sgrow * HID + sseg * 8;
    const __half* wSrc = Wm + (size_t)swr * HID + swseg * 8;
    uint32_t aDst = as_base + sr * 80 + sseg * 16;
    uint32_t wDst = ws_base + swr * 272 + swseg * 16;

    int a_row = wm + (lane & 15);
    int a_col = (lane >> 4) * 8;
    int g = lane >> 3;
    int b_krow = (lane & 7) + (g >> 1) * 8;
    int b_ncol = wn + (g & 1) * 8;

    cpa16(aDst, aSrc, sp);
    cpa16(aDst + 16, aSrc + 8, sp);
    cpa16(wDst, wSrc, true);
    cpa16(wDst + 16, wSrc + 8, true);
    cpcommit();

    #pragma unroll
    for (int i = 0; i < 4; i++) {
        if (i < 3) {
            int buf = (i + 1) & 1, kc = (i + 1) * 32;
            cpa16(aDst + buf * ABUF, aSrc + kc, sp);
            cpa16(aDst + buf * ABUF + 16, aSrc + kc + 8, sp);
            cpa16(wDst + buf * WBUF, wSrc + (size_t)kc * HID, true);
            cpa16(wDst + buf * WBUF + 16, wSrc + (size_t)kc * HID + 8, true);
            cpcommit();
            asm volatile("cp.async.wait_group 1;" ::: "memory");
        } else {
            asm volatile("cp.async.wait_group 0;" ::: "memory");
        }
        __syncthreads();
        int cur = i & 1;
        uint32_t a_b = as_base + cur * ABUF;
        uint32_t w_b = ws_base + cur * WBUF;

        #pragma unroll
        for (int ks = 0; ks < 32; ks += 16) {
            uint32_t a[2][4];
            #pragma unroll
            for (int mt = 0; mt < 2; mt++) {
                uint32_t addr = a_b + ((a_row + mt * 16) * 40 + ks + a_col) * 2;
                ldsm_x4(addr, a[mt][0], a[mt][1], a[mt][2], a[mt][3]);
            }
            uint32_t b[8][2];
            #pragma unroll
            for (int ntq = 0; ntq < 4; ntq++) {
                uint32_t addr = w_b + ((ks + b_krow) * 136 + b_ncol + ntq * 16) * 2;
                uint32_t r0, r1, r2, r3;
                ldsm_x4_t(addr, r0, r1, r2, r3);
                b[ntq * 2][0] = r0; b[ntq * 2 + 1][0] = r1;
                b[ntq * 2][1] = r2; b[ntq * 2 + 1][1] = r3;
            }
            #pragma unroll
            for (int mt = 0; mt < 2; mt++)
                #pragma unroll
                for (int nt = 0; nt < 8; nt++)
                    mma16816(acc[mt][nt], a[mt], b[nt][0], b[nt][1]);
        }
        __syncthreads();
    }

    // epilogue: scale by rsqrt(deg), convert to fp16, store
    int qr = lane >> 2, qc = (lane & 3) * 2;
    #pragma unroll
    for (int mt = 0; mt < 2; mt++) {
        int row_lo = m0 + wm + mt * 16 + qr;
        int row_hi = row_lo + 8;
        float sc_lo = (row_lo < NN) ? rsqrtf((float)g_cursor[row_lo] + 1.0f) : 0.f;
        float sc_hi = (row_hi < NN) ? rsqrtf((float)g_cursor[row_hi] + 1.0f) : 0.f;
        #pragma unroll
        for (int nt = 0; nt < 8; nt++) {
            int colg = wn + nt * 8 + qc;
            if (row_lo < NN) {
                half2 h = __floats2half2_rn(acc[mt][nt][0] * sc_lo, acc[mt][nt][1] * sc_lo);
                *(half2*)(g_tmp + (size_t)row_lo * HID + colg) = h;
            }
            if (row_hi < NN) {
                half2 h = __floats2half2_rn(acc[mt][nt][2] * sc_hi, acc[mt][nt][3] * sc_hi);
                *(half2*)(g_tmp + (size_t)row_hi * HID + colg) = h;
            }
        }
    }
}

__global__ void __launch_bounds__(256, 2) k_gemm1() {
    __shared__ __align__(16) __half As[2][128][40];
    __shared__ __align__(16) __half Ws[2][32][136];
    gemm_body(g_xh, g_w1h, blockIdx.x, &As[0][0][0], &Ws[0][0][0]);
}

__global__ void __launch_bounds__(256, 2) k_gemm2() {
    __shared__ __align__(16) __half As[2][128][40];
    __shared__ __align__(16) __half Ws[2][32][136];
    gemm_body(g_h1h, g_w2h, blockIdx.x, &As[0][0][0], &Ws[0][0][0]);
}

// ---------------- SpMM: out[d] = relu(dinv[d] * Σ_{s∈N(d)∪{d}} msg_scaled[s] + b)
// msg_scaled already carries dinv[src]; pure float4 adds at the L2 gather floor.
// DST=0: write fp16 g_h1h. DST=1: write fp32 outp (h2) + fp16 g_h2h.
template<int DST>
__global__ void k_spmm(const float* __restrict__ bias, float* __restrict__ outp) {
    int gw = (blockIdx.x * blockDim.x + threadIdx.x) >> 5;
    int lane = threadIdx.x & 31;
    if (gw >= NN) return;
    int cnt0 = g_cursor[gw];
    float dv = rsqrtf((float)cnt0 + 1.0f);
    int cnt = (cnt0 > PAD) ? PAD : cnt0;
    const int* cols = g_colp + (size_t)gw * PAD;
    const __half* tmp = (const __half*)g_tmp;

    float4 acc;
    {   // self-loop message (already scaled by dinv[gw])
        uint2 u = *(const uint2*)(tmp + (size_t)gw * HID + lane * 4);
        float2 a = __half22float2(*(half2*)&u.x), b = __half22float2(*(half2*)&u.y);
        acc = make_float4(a.x, a.y, b.x, b.y);
    }
    int j = 0;
    for (; j + 4 <= cnt; j += 4) {
        int s0 = cols[j], s1 = cols[j + 1], s2 = cols[j + 2], s3 = cols[j + 3];
        uint2 u0 = *(const uint2*)(tmp + (size_t)s0 * HID + lane * 4);
        uint2 u1 = *(const uint2*)(tmp + (size_t)s1 * HID + lane * 4);
        uint2 u2 = *(const uint2*)(tmp + (size_t)s2 * HID + lane * 4);
        uint2 u3 = *(const uint2*)(tmp + (size_t)s3 * HID + lane * 4);
        float2 a0 = __half22float2(*(half2*)&u0.x), b0 = __half22float2(*(half2*)&u0.y);
        float2 a1 = __half22float2(*(half2*)&u1.x), b1 = __half22float2(*(half2*)&u1.y);
        float2 a2 = __half22float2(*(half2*)&u2.x), b2 = __half22float2(*(half2*)&u2.y);
        float2 a3 = __half22float2(*(half2*)&u3.x), b3 = __half22float2(*(half2*)&u3.y);
        acc.x += a0.x + a1.x + a2.x + a3.x;
        acc.y += a0.y + a1.y + a2.y + a3.y;
        acc.z += b0.x + b1.x + b2.x + b3.x;
        acc.w += b0.y + b1.y + b2.y + b3.y;
    }
    for (; j < cnt; j++) {
        int s = cols[j];
        uint2 u = *(const uint2*)(tmp + (size_t)s * HID + lane * 4);
        float2 a = __half22float2(*(half2*)&u.x), b = __half22float2(*(half2*)&u.y);
        acc.x += a.x; acc.y += a.y; acc.z += b.x; acc.w += b.y;
    }

    float4 b4 = *(const float4*)(bias + lane * 4);
    float4 o;
    o.x = fmaxf(fmaf(acc.x, dv, b4.x), 0.f);
    o.y = fmaxf(fmaf(acc.y, dv, b4.y), 0.f);
    o.z = fmaxf(fmaf(acc.z, dv, b4.z), 0.f);
    o.w = fmaxf(fmaf(acc.w, dv, b4.w), 0.f);

    half2 ha = __floats2half2_rn(o.x, o.y);
    half2 hb = __floats2half2_rn(o.z, o.w);
    uint2 pk;
    pk.x = *(unsigned*)&ha; pk.y = *(unsigned*)&hb;
    if (DST == 0) {
        *(uint2*)(g_h1h + (size_t)gw * HID + lane * 4) = pk;
    } else {
        *(float4*)(outp + (size_t)gw * HID + lane * 4) = o;
        *(uint2*)(g_h2h + (size_t)gw * HID + lane * 4) = pk;
    }
}

// ---------------- head GEMM (HMMA) + trailing cursor-reset blocks ----------------
__global__ void __launch_bounds__(256)
k_head(const float* __restrict__ Wh, const float* __restrict__ bh, float* __restrict__ S) {
    __shared__ __align__(16) __half As[128][72];
    __shared__ __align__(16) __half Wsh[128][56];
    if (blockIdx.x >= GG) {   // cursor reset for next graph replay
        int i = (blockIdx.x - GG) * 256 + threadIdx.x;
        if (i < NN) g_cursor[i] = 0;
        return;
    }
    int t = threadIdx.x, lane = t & 31, wid = t >> 5;
    int m0 = blockIdx.x * 128;
    int wm = wid * 16;

    for (int i = t; i < 128 * 24; i += 256) {
        int r = i / 24, c2 = (i % 24) * 2;
        float lo = (c2 < NCLS) ? Wh[(size_t)r * NCLS + c2] : 0.f;
        float hi = (c2 + 1 < NCLS) ? Wh[(size_t)r * NCLS + c2 + 1] : 0.f;
        *(half2*)&Wsh[r][c2] = __floats2half2_rn(lo, hi);
    }

    float acc[6][4];
    #pragma unroll
    for (int nt = 0; nt < 6; nt++)
        #pragma unroll
        for (int q = 0; q < 4; q++) acc[nt][q] = 0.f;

    uint32_t as_base = (uint32_t)__cvta_generic_to_shared(&As[0][0]);
    uint32_t ws_base = (uint32_t)__cvta_generic_to_shared(&Wsh[0][0]);
    int a_row = wm + (lane & 15);
    int a_col = (lane >> 4) * 8;
    int g = lane >> 3;
    int b_krow = (lane & 7) + (g >> 1) * 8;
    int b_ncol = (g & 1) * 8;

    #pragma unroll
    for (int kc = 0; kc < HID; kc += 64) {
        {
            int r = t >> 1, cs = (t & 1) * 32;
            int grow = m0 + r;
            uint4 p0 = make_uint4(0,0,0,0), p1 = p0, p2 = p0, p3 = p0;
            if (grow < NN) {
                const uint4* src = (const uint4*)(g_h2h + (size_t)grow * HID + kc + cs);
                p0 = src[0]; p1 = src[1]; p2 = src[2]; p3 = src[3];
            }
            *(uint4*)&As[r][cs]      = p0;
            *(uint4*)&As[r][cs + 8]  = p1;
            *(uint4*)&As[r][cs + 16] = p2;
            *(uint4*)&As[r][cs + 24] = p3;
        }
        __syncthreads();

        #pragma unroll
        for (int ks = 0; ks < 64; ks += 16) {
            uint32_t a[4];
            ldsm_x4(as_base + (a_row * 72 + ks + a_col) * 2, a[0], a[1], a[2], a[3]);
            uint32_t b[6][2];
            #pragma unroll
            for (int ntq = 0; ntq < 3; ntq++) {
                uint32_t addr = ws_base + ((kc + ks + b_krow) * 56 + b_ncol + ntq * 16) * 2;
                uint32_t r0, r1, r2, r3;
                ldsm_x4_t(addr, r0, r1, r2, r3);
                b[ntq * 2][0] = r0; b[ntq * 2 + 1][0] = r1;
                b[ntq * 2][1] = r2; b[ntq * 2 + 1][1] = r3;
            }
            #pragma unroll
            for (int nt = 0; nt < 6; nt++)
                mma16816(acc[nt], a, b[nt][0], b[nt][1]);
        }
        __syncthreads();
    }

    int qr = lane >> 2, qc = (lane & 3) * 2;
    int row_lo = m0 + wm + qr, row_hi = row_lo + 8;
    #pragma unroll
    for (int nt = 0; nt < 5; nt++) {
        int col = nt * 8 + qc;
        float blo = bh[col], bhi = bh[col + 1];
        if (row_lo < NN) {
            S[(size_t)row_lo * NCLS + col]     = acc[nt][0] + blo;
            S[(size_t)row_lo * NCLS + col + 1] = acc[nt][1] + bhi;
        }
        if (row_hi < NN) {
            S[(size_t)row_hi * NCLS + col]     = acc[nt][2] + blo;
            S[(size_t)row_hi * NCLS + col + 1] = acc[nt][3] + bhi;
        }
    }
}

// ---------------- launch ----------------
extern "C" void kernel_launch(void* const* d_in, const int* in_sizes, int n_in,
                              void* d_out, int out_size) {
    const float* x   = (const float*)d_in[0];
    const void*  ei  = d_in[1];                 // int32 or int64, detected per fill block
    const float* W1  = (const float*)d_in[2];
    const float* b1  = (const float*)d_in[3];
    const float* W2  = (const float*)d_in[4];
    const float* b2  = (const float*)d_in[5];
    const float* Wh  = (const float*)d_in[6];
    const float* bh  = (const float*)d_in[7];

    float* out = (float*)d_out;
    float* scores = out;                       // [NN, 40]
    float* h2 = out + (size_t)NN * NCLS;       // [NN, 128]

    const int TB = 256;
    int spmm_grid = (NN * 32 + TB - 1) / TB;

    k_init<<<CONVB + FILLB, TB>>>(x, W1, W2, ei);   // converts || bucket fill
    k_gemm1<<<GG, TB>>>();
    k_spmm<0><<<spmm_grid, TB>>>(b1, nullptr);
    k_gemm2<<<GG, TB>>>();
    k_spmm<1><<<spmm_grid, TB>>>(b2, h2);
    k_head<<<GG + ZB, TB>>>(Wh, bh, scores);        // head + cursor reset
}

// round 15
// speedup vs baseline: 1.1907x; 1.0099x over previous
#include <cuda_runtime.h>
#include <cuda_fp16.h>
#include <cstdint>

// Problem constants
#define NN 100000
#define EE 1600000
#define HID 128
#define NCLS 40
#define GG 1563             // gemm blocks = ceil(NN/64)
#define HG 782              // head blocks = ceil(NN/128)
#define PAD 128             // bucket slots per destination node
#define WCONVB 16           // W-convert blocks in k_init
#define FILLB 6250          // fill blocks in k_init (EE/256)
#define ZB 391              // cursor-zero blocks appended to k_head

// ---------------- mma.sync / cp.async helpers ----------------
__device__ __forceinline__ void ldsm_x4(uint32_t addr, uint32_t& r0, uint32_t& r1,
                                        uint32_t& r2, uint32_t& r3) {
    asm volatile("ldmatrix.sync.aligned.m8n8.x4.shared.b16 {%0,%1,%2,%3}, [%4];"
                 : "=r"(r0), "=r"(r1), "=r"(r2), "=r"(r3) : "r"(addr));
}
__device__ __forceinline__ void ldsm_x4_t(uint32_t addr, uint32_t& r0, uint32_t& r1,
                                          uint32_t& r2, uint32_t& r3) {
    asm volatile("ldmatrix.sync.aligned.m8n8.x4.trans.shared.b16 {%0,%1,%2,%3}, [%4];"
                 : "=r"(r0), "=r"(r1), "=r"(r2), "=r"(r3) : "r"(addr));
}
__device__ __forceinline__ void mma16816(float c[4], const uint32_t a[4],
                                         uint32_t b0, uint32_t b1) {
    asm volatile(
        "mma.sync.aligned.m16n8k16.row.col.f32.f16.f16.f32 "
        "{%0,%1,%2,%3}, {%4,%5,%6,%7}, {%8,%9}, {%0,%1,%2,%3};"
        : "+f"(c[0]), "+f"(c[1]), "+f"(c[2]), "+f"(c[3])
        : "r"(a[0]), "r"(a[1]), "r"(a[2]), "r"(a[3]), "r"(b0), "r"(b1));
}
__device__ __forceinline__ void cpa16(uint32_t d, const void* s, bool p) {
    asm volatile("cp.async.cg.shared.global [%0], [%1], 16, %2;"
                 :: "r"(d), "l"(s), "r"(p ? 16 : 0));
}
__device__ __forceinline__ void cpcommit() { asm volatile("cp.async.commit_group;"); }

// ---------------- device scratch (static; no cudaMalloc allowed) ----------------
__device__ __half g_w1h[HID * HID];
__device__ __half g_w2h[HID * HID];
__device__ __half g_tmp[(size_t)NN * HID];  // fp16 messages, pre-scaled by dinv[src]
__device__ __half g_h1h[(size_t)NN * HID];  // layer-1 hidden, fp16
__device__ int    g_cursor[NN];             // in-degree (excl self loop); ZERO at entry
__device__ int    g_colp[(size_t)NN * PAD]; // padded buckets: sources per dst

// ---------------- K0: W fp16 converts || bucket fill ----------------
__global__ void __launch_bounds__(256)
k_init(const float* __restrict__ W1, const float* __restrict__ W2,
       const void* __restrict__ ei) {
    if (blockIdx.x < WCONVB) {
        int i = blockIdx.x * blockDim.x + threadIdx.x;   // 0..4095 = HID*HID/4
        float4 v = ((const float4*)W1)[i];
        half2 a = __floats2half2_rn(v.x, v.y), b = __floats2half2_rn(v.z, v.w);
        uint2 p; p.x = *(unsigned*)&a; p.y = *(unsigned*)&b;
        ((uint2*)g_w1h)[i] = p;
        float4 w = ((const float4*)W2)[i];
        half2 c = __floats2half2_rn(w.x, w.y), d = __floats2half2_rn(w.z, w.w);
        uint2 q; q.x = *(unsigned*)&c; q.y = *(unsigned*)&d;
        ((uint2*)g_w2h)[i] = q;
    } else {
        __shared__ int sfmt;
        if (threadIdx.x == 0) {
            const int* w = (const int*)ei;
            int is64 = 1;
            #pragma unroll
            for (int j = 1; j < 64; j += 2) is64 &= (w[j] == 0);
            sfmt = is64;
        }
        __syncthreads();
        int e = (blockIdx.x - WCONVB) * 256 + threadIdx.x;
        if (e < EE) {
            const int* w = (const int*)ei;
            int s, d;
            if (sfmt) { s = w[(size_t)e * 2]; d = w[((size_t)EE + e) * 2]; }
            else      { s = w[e];             d = w[(size_t)EE + e]; }
            if ((unsigned)d < NN) {
                int pos = atomicAdd(&g_cursor[d], 1);
                int c = ((unsigned)s < NN) ? s : d;
                if (pos < PAD) g_colp[(size_t)d * PAD + pos] = c;
            }
        }
    }
}

// ---------------- shared GEMM mainloop pieces (BM=64, BN=128, BK=32) ----------------
// smem bufs: A [64][40] halves (80B stride), W [32][136] halves (272B stride)
#define ABUF (64 * 40 * 2)
#define WBUF (32 * 136 * 2)

struct GemmCtx {
    uint32_t as_base, ws_base;
    int a_row, a_col, b_krow, b_ncol, wm, wn, m0;
};

__device__ __forceinline__ void gemm_setup(GemmCtx& c, int bid, void* As, void* Ws) {
    int t = threadIdx.x, lane = t & 31, wid = t >> 5;
    c.m0 = bid * 64;
    c.wm = (wid & 3) * 16;
    c.wn = (wid >> 2) * 64;
    c.as_base = (uint32_t)__cvta_generic_to_shared(As);
    c.ws_base = (uint32_t)__cvta_generic_to_shared(Ws);
    c.a_row = c.wm + (lane & 15);
    c.a_col = (lane >> 4) * 8;
    int g = lane >> 3;
    c.b_krow = (lane & 7) + (g >> 1) * 8;
    c.b_ncol = c.wn + (g & 1) * 8;
}

__device__ __forceinline__ void gemm_mma_chunk(const GemmCtx& c, int buf,
                                               float acc[8][4]) {
    uint32_t a_b = c.as_base + buf * ABUF;
    uint32_t w_b = c.ws_base + buf * WBUF;
    #pragma unroll
    for (int ks = 0; ks < 32; ks += 16) {
        uint32_t a[4];
        ldsm_x4(a_b + (c.a_row * 40 + ks + c.a_col) * 2, a[0], a[1], a[2], a[3]);
        uint32_t b[8][2];
        #pragma unroll
        for (int ntq = 0; ntq < 4; ntq++) {
            uint32_t addr = w_b + ((ks + c.b_krow) * 136 + c.b_ncol + ntq * 16) * 2;
            uint32_t r0, r1, r2, r3;
            ldsm_x4_t(addr, r0, r1, r2, r3);
            b[ntq * 2][0] = r0; b[ntq * 2 + 1][0] = r1;
            b[ntq * 2][1] = r2; b[ntq * 2 + 1][1] = r3;
        }
        #pragma unroll
        for (int nt = 0; nt < 8; nt++)
            mma16816(acc[nt], a, b[nt][0], b[nt][1]);
    }
}

// W staging via cp.async: chunk rows kc..kc+32, full 128 cols
__device__ __forceinline__ void stage_w(uint32_t ws_base, int buf,
                                        const __half* Wm, int kc) {
    int t = threadIdx.x;
    #pragma unroll
    for (int j = 0; j < 2; j++) {
        int i = t + j * 256;          // 0..511
        int row = i >> 4, c16 = i & 15;
        cpa16(ws_base + buf * WBUF + row * 272 + c16 * 16,
              Wm + (size_t)(kc + row) * HID + c16 * 8, true);
    }
}

// epilogue: scale by rsqrt(deg), fp16 store to g_tmp
__device__ __forceinline__ void gemm_epilogue(const GemmCtx& c, float acc[8][4]) {
    int lane = threadIdx.x & 31;
    int qr = lane >> 2, qc = (lane & 3) * 2;
    int row_lo = c.m0 + c.wm + qr;
    int row_hi = row_lo + 8;
    float sc_lo = (row_lo < NN) ? rsqrtf((float)g_cursor[row_lo] + 1.0f) : 0.f;
    float sc_hi = (row_hi < NN) ? rsqrtf((float)g_cursor[row_hi] + 1.0f) : 0.f;
    #pragma unroll
    for (int nt = 0; nt < 8; nt++) {
        int colg = c.wn + nt * 8 + qc;
        if (row_lo < NN) {
            half2 h = __floats2half2_rn(acc[nt][0] * sc_lo, acc[nt][1] * sc_lo);
            *(half2*)(g_tmp + (size_t)row_lo * HID + colg) = h;
        }
        if (row_hi < NN) {
            half2 h = __floats2half2_rn(acc[nt][2] * sc_hi, acc[nt][3] * sc_hi);
            *(half2*)(g_tmp + (size_t)row_hi * HID + colg) = h;
        }
    }
}

// ---------------- K1: GEMM layer 1, fp32 x source with inline convert ----------------
__global__ void __launch_bounds__(256, 3)
k_gemm1(const float* __restrict__ x) {
    __shared__ __align__(16) __half As[2][64][40];
    __shared__ __align__(16) __half Ws[2][32][136];
    GemmCtx c;
    gemm_setup(c, blockIdx.x, &As[0][0][0], &Ws[0][0][0]);
    int t = threadIdx.x;

    float acc[8][4];
    #pragma unroll
    for (int nt = 0; nt < 8; nt++)
        #pragma unroll
        for (int q = 0; q < 4; q++) acc[nt][q] = 0.f;

    // A staging geometry: thread t -> row t>>2, col (t&3)*8 (8 floats -> 16B fp16)
    int srow = t >> 2, scol = (t & 3) * 8;
    int sgrow = c.m0 + srow;
    bool sp = sgrow < NN;
    const float* aSrc = x + (size_t)sgrow * HID + scol;
    uint32_t aDst = c.as_base + srow * 80 + scol * 2;

    float4 c0 = make_float4(0,0,0,0), c1 = c0;
    if (sp) { c0 = *(const float4*)aSrc; c1 = *(const float4*)(aSrc + 4); }
    stage_w(c.ws_base, 0, g_w1h, 0);
    cpcommit();

    #pragma unroll
    for (int i = 0; i < 4; i++) {
        float4 n0 = make_float4(0,0,0,0), n1 = n0;
        if (i < 3) {
            int kc = (i + 1) * 32;
            if (sp) { n0 = *(const float4*)(aSrc + kc); n1 = *(const float4*)(aSrc + kc + 4); }
            stage_w(c.ws_base, (i + 1) & 1, g_w2h == nullptr ? g_w1h : g_w1h, kc); // W1
            cpcommit();
        }
        // convert + STS current A chunk into buf i&1
        {
            half2 h0 = __floats2half2_rn(c0.x, c0.y), h1 = __floats2half2_rn(c0.z, c0.w);
            half2 h2 = __floats2half2_rn(c1.x, c1.y), h3 = __floats2half2_rn(c1.z, c1.w);
            uint4 p;
            p.x = *(unsigned*)&h0; p.y = *(unsigned*)&h1;
            p.z = *(unsigned*)&h2; p.w = *(unsigned*)&h3;
            *(uint4*)((char*)As + (i & 1) * ABUF + srow * 80 + scol * 2) = p;
        }
        if (i < 3) asm volatile("cp.async.wait_group 1;" ::: "memory");
        else       asm volatile("cp.async.wait_group 0;" ::: "memory");
        __syncthreads();
        gemm_mma_chunk(c, i & 1, acc);
        __syncthreads();
        c0 = n0; c1 = n1;
    }
    gemm_epilogue(c, acc);
}

// ---------------- K3: GEMM layer 2, fp16 g_h1h source (all cp.async) ----------------
__global__ void __launch_bounds__(256, 3)
k_gemm2() {
    __shared__ __align__(16) __half As[2][64][40];
    __shared__ __align__(16) __half Ws[2][32][136];
    GemmCtx c;
    gemm_setup(c, blockIdx.x, &As[0][0][0], &Ws[0][0][0]);
    int t = threadIdx.x;

    float acc[8][4];
    #pragma unroll
    for (int nt = 0; nt < 8; nt++)
        #pragma unroll
        for (int q = 0; q < 4; q++) acc[nt][q] = 0.f;

    // A staging: thread t -> one 16B seg: row t>>2, seg t&3 (8 halves)
    int srow = t >> 2, sseg = t & 3;
    int sgrow = c.m0 + srow;
    bool sp = sgrow < NN;
    const __half* aSrc = g_h1h + (size_t)sgrow * HID + sseg * 8;
    uint32_t aDst = c.as_base + srow * 80 + sseg * 16;

    cpa16(aDst, aSrc, sp);
    stage_w(c.ws_base, 0, g_w2h, 0);
    cpcommit();

    #pragma unroll
    for (int i = 0; i < 4; i++) {
        if (i < 3) {
            int buf = (i + 1) & 1, kc = (i + 1) * 32;
            cpa16(aDst + buf * ABUF, aSrc + kc, sp);
            stage_w(c.ws_base, buf, g_w2h, kc);
            cpcommit();
            asm volatile("cp.async.wait_group 1;" ::: "memory");
        } else {
            asm volatile("cp.async.wait_group 0;" ::: "memory");
        }
        __syncthreads();
        gemm_mma_chunk(c, i & 1, acc);
        __syncthreads();
    }
    gemm_epilogue(c, acc);
}

// ---------------- SpMM: out[d] = relu(dinv[d] * Σ msg_scaled + b) ----------------
// DST=0: write fp16 g_h1h. DST=1: write fp32 outp (h2).
template<int DST>
__global__ void k_spmm(const float* __restrict__ bias, float* __restrict__ outp) {
    int gw = (blockIdx.x * blockDim.x + threadIdx.x) >> 5;
    int lane = threadIdx.x & 31;
    if (gw >= NN) return;
    int cnt0 = g_cursor[gw];
    float dv = rsqrtf((float)cnt0 + 1.0f);
    int cnt = (cnt0 > PAD) ? PAD : cnt0;
    const int* cols = g_colp + (size_t)gw * PAD;
    const __half* tmp = (const __half*)g_tmp;

    float4 acc;
    {   // self-loop message (already scaled by dinv[gw])
        uint2 u = *(const uint2*)(tmp + (size_t)gw * HID + lane * 4);
        float2 a = __half22float2(*(half2*)&u.x), b = __half22float2(*(half2*)&u.y);
        acc = make_float4(a.x, a.y, b.x, b.y);
    }
    int j = 0;
    for (; j + 4 <= cnt; j += 4) {
        int s0 = cols[j], s1 = cols[j + 1], s2 = cols[j + 2], s3 = cols[j + 3];
        uint2 u0 = *(const uint2*)(tmp + (size_t)s0 * HID + lane * 4);
        uint2 u1 = *(const uint2*)(tmp + (size_t)s1 * HID + lane * 4);
        uint2 u2 = *(const uint2*)(tmp + (size_t)s2 * HID + lane * 4);
        uint2 u3 = *(const uint2*)(tmp + (size_t)s3 * HID + lane * 4);
        float2 a0 = __half22float2(*(half2*)&u0.x), b0 = __half22float2(*(half2*)&u0.y);
        float2 a1 = __half22float2(*(half2*)&u1.x), b1 = __half22float2(*(half2*)&u1.y);
        float2 a2 = __half22float2(*(half2*)&u2.x), b2 = __half22float2(*(half2*)&u2.y);
        float2 a3 = __half22float2(*(half2*)&u3.x), b3 = __half22float2(*(half2*)&u3.y);
        acc.x += a0.x + a1.x + a2.x + a3.x;
        acc.y += a0.y + a1.y + a2.y + a3.y;
        acc.z += b0.x + b1.x + b2.x + b3.x;
        acc.w += b0.y + b1.y + b2.y + b3.y;
    }
    for (; j < cnt; j++) {
        int s = cols[j];
        uint2 u = *(const uint2*)(tmp + (size_t)s * HID + lane * 4);
        float2 a = __half22float2(*(half2*)&u.x), b = __half22float2(*(half2*)&u.y);
        acc.x += a.x; acc.y += a.y; acc.z += b.x; acc.w += b.y;
    }

    float4 b4 = *(const float4*)(bias + lane * 4);
    float4 o;
    o.x = fmaxf(fmaf(acc.x, dv, b4.x), 0.f);
    o.y = fmaxf(fmaf(acc.y, dv, b4.y), 0.f);
    o.z = fmaxf(fmaf(acc.z, dv, b4.z), 0.f);
    o.w = fmaxf(fmaf(acc.w, dv, b4.w), 0.f);

    if (DST == 0) {
        half2 ha = __floats2half2_rn(o.x, o.y);
        half2 hb = __floats2half2_rn(o.z, o.w);
        uint2 pk;
        pk.x = *(unsigned*)&ha; pk.y = *(unsigned*)&hb;
        *(uint2*)(g_h1h + (size_t)gw * HID + lane * 4) = pk;
    } else {
        *(float4*)(outp + (size_t)gw * HID + lane * 4) = o;
    }
}

// ---------------- head GEMM (HMMA, fp32 h2 source) + cursor-reset blocks ----------
__global__ void __launch_bounds__(256)
k_head(const float* __restrict__ H2, const float* __restrict__ Wh,
       const float* __restrict__ bh, float* __restrict__ S) {
    __shared__ __align__(16) __half As[128][72];
    __shared__ __align__(16) __half Wsh[128][56];
    if (blockIdx.x >= HG) {   // cursor reset for next graph replay
        int i = (blockIdx.x - HG) * 256 + threadIdx.x;
        if (i < NN) g_cursor[i] = 0;
        return;
    }
    int t = threadIdx.x, lane = t & 31, wid = t >> 5;
    int m0 = blockIdx.x * 128;
    int wm = wid * 16;

    for (int i = t; i < 128 * 24; i += 256) {
        int r = i / 24, c2 = (i % 24) * 2;
        float lo = (c2 < NCLS) ? Wh[(size_t)r * NCLS + c2] : 0.f;
        float hi = (c2 + 1 < NCLS) ? Wh[(size_t)r * NCLS + c2 + 1] : 0.f;
        *(half2*)&Wsh[r][c2] = __floats2half2_rn(lo, hi);
    }

    float acc[6][4];
    #pragma unroll
    for (int nt = 0; nt < 6; nt++)
        #pragma unroll
        for (int q = 0; q < 4; q++) acc[nt][q] = 0.f;

    uint32_t as_base = (uint32_t)__cvta_generic_to_shared(&As[0][0]);
    uint32_t ws_base = (uint32_t)__cvta_generic_to_shared(&Wsh[0][0]);
    int a_row = wm + (lane & 15);
    int a_col = (lane >> 4) * 8;
    int g = lane >> 3;
    int b_krow = (lane & 7) + (g >> 1) * 8;
    int b_ncol = (g & 1) * 8;

    #pragma unroll
    for (int kc = 0; kc < HID; kc += 64) {
        {   // stage fp32 h2 chunk [128][64] with inline convert
            int r = t >> 1, cs = (t & 1) * 32;
            int grow = m0 + r;
            const float* src = H2 + (size_t)grow * HID + kc + cs;
            #pragma unroll
            for (int q = 0; q < 4; q++) {
                float4 v0 = make_float4(0,0,0,0), v1 = v0;
                if (grow < NN) {
                    v0 = *(const float4*)(src + q * 8);
                    v1 = *(const float4*)(src + q * 8 + 4);
                }
                half2 h0 = __floats2half2_rn(v0.x, v0.y), h1 = __floats2half2_rn(v0.z, v0.w);
                half2 h2 = __floats2half2_rn(v1.x, v1.y), h3 = __floats2half2_rn(v1.z, v1.w);
                uint4 p;
                p.x = *(unsigned*)&h0; p.y = *(unsigned*)&h1;
                p.z = *(unsigned*)&h2; p.w = *(unsigned*)&h3;
                *(uint4*)&As[r][cs + q * 8] = p;
            }
        }
        __syncthreads();

        #pragma unroll
        for (int ks = 0; ks < 64; ks += 16) {
            uint32_t a[4];
            ldsm_x4(as_base + (a_row * 72 + ks + a_col) * 2, a[0], a[1], a[2], a[3]);
            uint32_t b[6][2];
            #pragma unroll
            for (int ntq = 0; ntq < 3; ntq++) {
                uint32_t addr = ws_base + ((kc + ks + b_krow) * 56 + b_ncol + ntq * 16) * 2;
                uint32_t r0, r1, r2, r3;
                ldsm_x4_t(addr, r0, r1, r2, r3);
                b[ntq * 2][0] = r0; b[ntq * 2 + 1][0] = r1;
                b[ntq * 2][1] = r2; b[ntq * 2 + 1][1] = r3;
            }
            #pragma unroll
            for (int nt = 0; nt < 6; nt++)
                mma16816(acc[nt], a, b[nt][0], b[nt][1]);
        }
        __syncthreads();
    }

    int qr = lane >> 2, qc = (lane & 3) * 2;
    int row_lo = m0 + wm + qr, row_hi = row_lo + 8;
    #pragma unroll
    for (int nt = 0; nt < 5; nt++) {
        int col = nt * 8 + qc;
        float blo = bh[col], bhi = bh[col + 1];
        if (row_lo < NN) {
            S[(size_t)row_lo * NCLS + col]     = acc[nt][0] + blo;
            S[(size_t)row_lo * NCLS + col + 1] = acc[nt][1] + bhi;
        }
        if (row_hi < NN) {
            S[(size_t)row_hi * NCLS + col]     = acc[nt][2] + blo;
            S[(size_t)row_hi * NCLS + col + 1] = acc[nt][3] + bhi;
        }
    }
}

// ---------------- launch ----------------
extern "C" void kernel_launch(void* const* d_in, const int* in_sizes, int n_in,
                              void* d_out, int out_size) {
    const float* x   = (const float*)d_in[0];
    const void*  ei  = d_in[1];                 // int32 or int64, detected per fill block
    const float* W1  = (const float*)d_in[2];
    const float* b1  = (const float*)d_in[3];
    const float* W2  = (const float*)d_in[4];
    const float* b2  = (const float*)d_in[5];
    const float* Wh  = (const float*)d_in[6];
    const float* bh  = (const float*)d_in[7];

    float* out = (float*)d_out;
    float* scores = out;                       // [NN, 40]
    float* h2 = out + (size_t)NN * NCLS;       // [NN, 128]

    const int TB = 256;
    int spmm_grid = (NN * 32 + TB - 1) / TB;

    k_init<<<WCONVB + FILLB, TB>>>(W1, W2, ei);   // W converts || bucket fill
    k_gemm1<<<GG, TB>>>(x);
    k_spmm<0><<<spmm_grid, TB>>>(b1, nullptr);
    k_gemm2<<<GG, TB>>>();
    k_spmm<1><<<spmm_grid, TB>>>(b2, h2);
    k_head<<<HG + ZB, TB>>>(h2, Wh, bh, scores);  // head + cursor reset
}